// round 17
// baseline (speedup 1.0000x reference)
#include <cuda_runtime.h>
#include <cuda_bf16.h>

#define NSEG 65
#define NCOPY 32            // global histogram copies (indexed by cta & 31)
#define EPSF 1e-5f

// Shared-path packed slot: bits[20:32)=count, bits[0:20)=sum in Q12.
// 3542 voxels/block on this path -> bin Poisson(54.5), P(>255)~0;
// 255*4096 < 2^20: no carry.
#define CNT_ONE  (1u << 20)
#define SUM_MASK ((1u << 20) - 1u)
#define Q12      4096.0f
#define INV_Q12  2.44140625e-4f
// Global-path packed slot: bits[20:32)=count, bits[0:20)=sum in Q8.
// Max 10 CTAs/copy * 3542 voxels -> bin <~1300: 1300*256=333k < 2^20,
// count 1300 < 4096. Q8 rounding -> ~1e-5 relative error on inter.
#define Q8       256.0f
#define INV_Q8   3.90625e-3f

// Global scratch (zero-init; last block re-zeroes after each run).
__device__ float        g_inter[2 * NSEG];
__device__ unsigned int g_cnt[2 * NSEG];
__device__ unsigned int g_part[NCOPY * 2 * NSEG];   // L2-resident partials
__device__ unsigned int g_done;

// 256-bit loads (sm_100 allows inline .L2::evict_* only on .v8.b32/.v4.b64).
#define LDG256(P, R)                                                          \
    asm("ld.global.nc.L2::evict_last.v8.b32 {%0,%1,%2,%3,%4,%5,%6,%7}, [%8];" \
        : "=r"((R)[0]), "=r"((R)[1]), "=r"((R)[2]), "=r"((R)[3]),             \
          "=r"((R)[4]), "=r"((R)[5]), "=r"((R)[6]), "=r"((R)[7])              \
        : "l"(P))

__device__ __forceinline__ float cc_sig(float x0, float x1, int yv, float scale) {
    // softmax over C=2 at the true channel = sigmoid(x_true - x_other)
    float d = __int_as_float(__float_as_int(x0 - x1) ^ (yv << 31));
    return __fdividef(scale, 1.0f + __expf(-d));
}

// MIO pipe: shared atomic, fire-and-forget. 1 lane-op.
__device__ __forceinline__ void cc_proc_s(float x0, float x1, int yv, int sv,
                                          unsigned int* s_hist) {
    unsigned q = __float2uint_rn(cc_sig(x0, x1, yv, Q12));
    atomicAdd(&s_hist[sv], CNT_ONE + q);   // bin 0 = write-only trash
}

// LSU/L2 pipe: global RED (no return -> REDG), per-CTA-strided copy.
__device__ __forceinline__ void cc_proc_g(float x0, float x1, int yv, int sv,
                                          unsigned int* gslot) {
    unsigned q = __float2uint_rn(cc_sig(x0, x1, yv, Q8));
    atomicAdd(&gslot[sv], CNT_ONE + q);    // bin 0 = write-only trash
}

__global__ __launch_bounds__(256, 4)
void cc_fused_kernel(const float* __restrict__ pred,
                     const void*  __restrict__ y,
                     const void*  __restrict__ vor,
                     int N, int total_blocks,
                     float* __restrict__ out) {
    __shared__ unsigned int s_hist[NSEG];
    __shared__ int s_is64;
    __shared__ int s_last;

    const int b   = blockIdx.y;
    const int tid = threadIdx.x;

    // --- dtype probe (warp 0): int64 labels in [0,64] => all odd 32-bit
    // words zero. Measured flushed-DRAM traffic (67.5 MB = exact int32
    // footprint) says data is int32; the int64 branch is a fallback only.
    if (tid < 32) {
        unsigned odd = ((const unsigned int*)vor)[2 * tid + 1];
        unsigned any = __ballot_sync(0xffffffffu, odd != 0u);
        if (tid == 0) s_is64 = (any == 0u);
    }
    for (int i = tid; i < NSEG; i += blockDim.x) s_hist[i] = 0u;
    __syncthreads();

    // this block's global partial-histogram copy (65 words in L2)
    unsigned int* gslot = g_part + ((blockIdx.x & (NCOPY - 1)) * 2 + b) * NSEG;

    const float* p0 = pred + (size_t)b * 2 * N;
    const float* p1 = p0 + N;

    const unsigned gtid   = blockIdx.x * blockDim.x + tid;
    const unsigned stride = gridDim.x * blockDim.x;
    const unsigned n8     = (unsigned)N >> 3;

    if (!s_is64) {
        // ---- FAST PATH: int32 labels. 4 x 32B loads per 8 voxels.
        // Voxels 0-3 -> shared ATOMS (MIO pipe); 4-7 -> global RED (L2 pipe).
        const int* ys = (const int*)y   + (size_t)b * N;
        const int* vs = (const int*)vor + (size_t)b * N;
        for (unsigned i = gtid; i < n8; i += stride) {
            unsigned a0[8], a1[8], yA[8], vA[8];
            LDG256(p0 + 8u * i, a0);
            LDG256(p1 + 8u * i, a1);
            LDG256(ys + 8u * i, yA);
            LDG256(vs + 8u * i, vA);
            #pragma unroll
            for (int k = 0; k < 4; k++)
                cc_proc_s(__uint_as_float(a0[k]), __uint_as_float(a1[k]),
                          (int)yA[k], (int)vA[k], s_hist);
            #pragma unroll
            for (int k = 4; k < 8; k++)
                cc_proc_g(__uint_as_float(a0[k]), __uint_as_float(a1[k]),
                          (int)yA[k], (int)vA[k], gslot);
        }
        for (unsigned i = (n8 << 3) + gtid; i < (unsigned)N; i += stride)
            cc_proc_s(p0[i], p1[i], ys[i], vs[i], s_hist);
    } else {
        // ---- FALLBACK: int64 labels (16B loads). ----
        const long long* ys = (const long long*)y   + (size_t)b * N;
        const long long* vs = (const long long*)vor + (size_t)b * N;
        const float4* x0 = (const float4*)p0;
        const float4* x1 = (const float4*)p1;
        const unsigned n4 = (unsigned)N >> 2;
        for (unsigned i = gtid; i < n4; i += stride) {
            float4 a = __ldg(&x0[i]);
            float4 c = __ldg(&x1[i]);
            longlong2 ya = __ldg((const longlong2*)(ys + 4u * i));
            longlong2 yc = __ldg((const longlong2*)(ys + 4u * i + 2));
            longlong2 va = __ldg((const longlong2*)(vs + 4u * i));
            longlong2 vc = __ldg((const longlong2*)(vs + 4u * i + 2));
            cc_proc_s(a.x, c.x, (int)ya.x, (int)va.x, s_hist);
            cc_proc_s(a.y, c.y, (int)ya.y, (int)va.y, s_hist);
            cc_proc_g(a.z, c.z, (int)yc.x, (int)vc.x, gslot);
            cc_proc_g(a.w, c.w, (int)yc.y, (int)vc.y, gslot);
        }
        for (unsigned i = (n4 << 2) + gtid; i < (unsigned)N; i += stride)
            cc_proc_s(p0[i], p1[i], (int)ys[i], (int)vs[i], s_hist);
    }

    __syncthreads();

    // shared-path unpack -> global accumulators (skip trash bin 0)
    for (int i = tid; i < NSEG; i += blockDim.x) {
        unsigned int pk = s_hist[i];
        if (pk && i != 0) {
            atomicAdd(&g_inter[b * NSEG + i], (float)(pk & SUM_MASK) * INV_Q12);
            atomicAdd(&g_cnt[b * NSEG + i], pk >> 20);
        }
    }

    // --- last-block finalize + re-zero (keeps graph replays deterministic)
    __threadfence();   // orders our REDs + adds before the done-count
    if (tid == 0) {
        unsigned int v = atomicAdd(&g_done, 1u);
        s_last = (v == (unsigned int)(total_blocks - 1));
    }
    __syncthreads();
    if (!s_last) return;

    __shared__ float sd[2][64];
    __shared__ float sp[2][64];
    int t = tid;
    if (t < 128) {
        int bb = t >> 6, l = (t & 63) + 1;
        // merge shared-path totals with the 32 global partial copies
        unsigned int c  = g_cnt[bb * NSEG + l];
        float        it = g_inter[bb * NSEG + l];
        unsigned int gsum = 0, gcnt = 0;
        #pragma unroll 4
        for (int cp = 0; cp < NCOPY; cp++) {
            unsigned int pk = g_part[(cp * 2 + bb) * NSEG + l];
            gcnt += pk >> 20;
            gsum += pk & SUM_MASK;
        }
        c  += gcnt;
        it += (float)gsum * INV_Q8;
        // psum + tsum == 2*cnt exactly (softmax rows sum to 1)
        float dice = (2.0f * it + EPSF) / (2.0f * (float)c + EPSF);
        sd[bb][t & 63] = (c > 0u) ? dice : 0.0f;
        sp[bb][t & 63] = (c > 0u) ? 1.0f : 0.0f;
    }
    __syncthreads();
    if (t == 0) {
        float total = 0.0f;
        for (int bb = 0; bb < 2; bb++) {
            float sum = 0.0f, np = 0.0f;
            for (int i = 0; i < 64; i++) { sum += sd[bb][i]; np += sp[bb][i]; }
            if (np < 1.0f) np = 1.0f;
            total += sum / np;
        }
        out[0] = 0.5f * total;
    }
    // re-zero ALL state for the next replay (reads above are done: __syncthreads)
    for (int i = t; i < NCOPY * 2 * NSEG; i += blockDim.x) g_part[i] = 0u;
    if (t < 2 * NSEG) { g_inter[t] = 0.0f; g_cnt[t] = 0u; }
    if (t == 0) g_done = 0u;
}

extern "C" void kernel_launch(void* const* d_in, const int* in_sizes, int n_in,
                              void* d_out, int out_size) {
    const float* pred = (const float*)d_in[0];  // y_pred [B,2,H,W,D] f32
    const void*  y    = d_in[1];                // y      [B,1,H,W,D] int32 (int64 fallback)
    const void*  vor  = d_in[2];                // voronoi[B,H,W,D]   int32 (int64 fallback)

    const int B = 2;
    const int N = in_sizes[2] / B;              // voxels per sample (H*W*D)

    // 296 x 2 = 592 CTAs = exactly 4 resident CTAs per SM (single wave)
    dim3 grid(296, B);
    cc_fused_kernel<<<grid, 256>>>(pred, y, vor, N, (int)(grid.x * grid.y),
                                   (float*)d_out);
}